// round 11
// baseline (speedup 1.0000x reference)
#include <cuda_runtime.h>

#define NT    1024
#define PG    8                  // points per group (= n_steps-2 here)
#define DD    64
#define HH    2048
#define CCH   512                // chunk columns
#define LD    516                // padded row stride (floats): 4 mod 32
#define HOFF  258                // h-half offset inside a row: 2 mod 32, 8B-aligned
#define NCHK  4
#define MAXB  64

__device__ float g_wpart[MAXB * NCHK * DD * PG];
__device__ float g_cpart[MAXB * NCHK * DD * PG];
__device__ unsigned g_cntA[MAXB];
__device__ unsigned g_cntB[MAXB];

__device__ __forceinline__ float tanh_fast(float x)
{
    float y;
    asm("tanh.approx.f32 %0, %1;" : "=f"(y) : "f"(x));
    return y;
}

// h-split offset of logical column j within a padded row
__device__ __forceinline__ int joffs(int j) { return (j >> 8) * HOFF + (j & 255); }

// stage one 64x512 W1 tile into smem in h-split layout.
// 8-byte cp.async.ca: destination only needs 8B alignment (HOFF*4 = 1032 B is 8B-aligned).
__device__ __forceinline__ void load_chunk_async(float* buf, const float* __restrict__ W1,
                                                 int j0, int tid)
{
    #pragma unroll
    for (int s = 0; s < 16; ++s) {
        int seg = s * NT + tid;          // 16384 8B segments
        int row = seg >> 8;              // 0..63
        int k   = seg & 255;             // 8B segment within row (256 per row)
        const float* src = W1 + row * HH + j0 + k * 2;
        int dstf = row * LD + (k >> 7) * HOFF + (k & 127) * 2;
        unsigned dst = (unsigned)__cvta_generic_to_shared(buf + dstf);
        asm volatile("cp.async.ca.shared.global [%0], [%1], 8;" :: "r"(dst), "l"(src));
    }
    asm volatile("cp.async.commit_group;");
}

// row pass over 512 j, split across h-halves; lane = (rs<<4)|(p<<1)|h
// W instruction: 4 distinct float2 addrs (banks {0,2,4,6}+pairs), 8-lane broadcast.
// A instruction: 16 distinct float2 addrs at banks 4p+2h -> all 32 banks once.
__device__ __forceinline__ void row_pass(const float* __restrict__ W1s,
                                         const float* __restrict__ src_p,   // [p][LD] h-split
                                         float* __restrict__ dstg,          // [DD*PG]
                                         int lane, int warp)
{
    int h  = lane & 1;
    int p  = (lane >> 1) & 7;
    int rs = lane >> 4;
    int row = warp * 2 + rs;
    const float2* Wp = (const float2*)(W1s + row * LD + h * HOFF);
    const float2* Ap = (const float2*)(src_p + p * LD + h * HOFF);
    float a0 = 0.f, a1 = 0.f;
    #pragma unroll 8
    for (int j2 = 0; j2 < 128; j2 += 2) {
        float2 w0 = Wp[j2],     w1 = Wp[j2 + 1];
        float2 b0 = Ap[j2],     b1 = Ap[j2 + 1];
        a0 += w0.x * b0.x + w0.y * b0.y;
        a1 += w1.x * b1.x + w1.y * b1.y;
    }
    float tot = a0 + a1;
    tot += __shfl_xor_sync(0xffffffffu, tot, 1);
    if (h == 0) dstg[row * PG + p] = tot;
}

__global__ __launch_bounds__(NT, 1) void geo_one(
    const float* __restrict__ x0, const float* __restrict__ xT,
    const float* __restrict__ W1, const float* __restrict__ b1,
    const float* __restrict__ W2, float* __restrict__ out,
    int B, int O, int n_steps, int nInterior)
{
    extern __shared__ float sm[];
    float* W1s   = sm;                   // DD*LD = 33024
    float* a_sh  = W1s + DD * LD;        // 512
    float* asp_p = a_sh + CCH;           // [p][LD] h-split : 8*516
    float* as_p  = asp_p + PG * LD;      // 8*516
    float* ue    = as_p + PG * LD;       // [2][512]
    float* wp    = ue + 2 * CCH;         // [d][p] : 512
    float* csh   = wp + DD * PG;         // [p][d] : 512
    float* x0g   = csh + PG * DD;        // 64
    float* dlt   = x0g + DD;             // 64
    float* red   = dlt + DD;             // 16
    __shared__ int slast;

    int tid = threadIdx.x, lane = tid & 31, warp = tid >> 5;
    int g = blockIdx.x;                  // batch index
    int c = blockIdx.y;                  // W1 chunk
    int j0 = c * CCH;
    int nsPerB = n_steps - 2;            // <= PG
    float invn1 = 1.0f / (float)(n_steps - 1);

    load_chunk_async(W1s, W1, j0, tid);

    // ---------- prep ----------
    if (tid < DD) {
        float a0 = x0[g * DD + tid];
        float aT = xT[g * DD + tid];
        x0g[tid] = a0;
        dlt[tid] = aT - a0;
        if (c == 0) {
            out[g * DD + tid] = a0;
            out[((n_steps - 1) * B + g) * DD + tid] = aT;
        }
    }
    __syncthreads();
    if (warp == 0) {
        float s = dlt[lane] * dlt[lane] + dlt[lane + 32] * dlt[lane + 32];
        #pragma unroll
        for (int o = 16; o; o >>= 1) s += __shfl_xor_sync(0xffffffffu, s, o);
        if (lane == 0) red[0] = 1.0f / sqrtf(s);
    }
    __syncthreads();

    // a_j = inv * (W2[j,:] . dlt) for this chunk's 512 j
    if (tid < CCH) {
        float inv = red[0];
        const float4* w2r = (const float4*)(W2 + (size_t)(j0 + tid) * O);
        const float4* v4  = (const float4*)dlt;
        float acc = 0.f;
        #pragma unroll
        for (int k = 0; k < DD / 4; ++k) {
            float4 w = w2r[k], vv = v4[k];
            acc += w.x * vv.x + w.y * vv.y + w.z * vv.z + w.w * vv.w;
        }
        a_sh[tid] = acc * inv;
    }
    asm volatile("cp.async.wait_group 0;");
    __syncthreads();

    int j   = tid & (CCH - 1);
    int ph  = tid >> 9;                  // 0 or 1
    int jo  = joffs(j);

    // ---------- phase A column: u_j (ph=0) / e_j (ph=1) ----------
    {
        const float* src = ph ? dlt : x0g;
        float acc = ph ? 0.f : b1[j0 + j];
        #pragma unroll 8
        for (int d = 0; d < DD; ++d)
            acc += src[d] * W1s[d * LD + jo];
        ue[ph * CCH + j] = acc;
    }
    __syncthreads();

    // as/asp for this thread's 4 points
    {
        float u = ue[j], e = ue[CCH + j];
        float a = a_sh[j];
        #pragma unroll
        for (int k = 0; k < 4; ++k) {
            int p = ph * 4 + k;
            int pc = (p < nsPerB) ? p : (nsPerB - 1);
            float tpar = (float)(pc + 1) * invn1;
            float t = tanh_fast(u + tpar * e);
            float sf = 1.0f - t * t;
            as_p[p * LD + jo]  = a * sf;
            asp_p[p * LD + jo] = a * (-2.0f * t * sf);
        }
    }
    __syncthreads();

    // ---------- phase A row: partial w ----------
    row_pass(W1s, as_p, &g_wpart[(g * NCHK + c) * DD * PG], lane, warp);

    // ---------- gate A ----------
    __syncthreads();
    __threadfence();
    if (tid == 0) {
        atomicAdd(&g_cntA[g], 1u);
        while (((volatile unsigned*)g_cntA)[g] < NCHK) __nanosleep(20);
    }
    __syncthreads();

    // ---------- phase B: reduce w ; q ; m ----------
    if (tid < DD * PG) {
        float s = 0.f;
        #pragma unroll
        for (int cc = 0; cc < NCHK; ++cc)
            s += __ldcg(&g_wpart[(g * NCHK + cc) * DD * PG + tid]);
        wp[tid] = s;
    }
    __syncthreads();

    {
        float q0 = 0.f, q1 = 0.f, q2 = 0.f, q3 = 0.f;
        const float4* wp4 = (const float4*)wp;
        #pragma unroll 8
        for (int d = 0; d < DD; ++d) {
            float wv = W1s[d * LD + jo];
            float4 wc = wp4[d * 2 + ph];
            q0 += wc.x * wv; q1 += wc.y * wv; q2 += wc.z * wv; q3 += wc.w * wv;
        }
        float qv[4] = {q0, q1, q2, q3};
        #pragma unroll
        for (int k = 0; k < 4; ++k) {
            int p = ph * 4 + k;
            as_p[p * LD + jo] = asp_p[p * LD + jo] * qv[k];
        }
    }
    __syncthreads();

    // ---------- phase B row: partial corr ----------
    row_pass(W1s, as_p, &g_cpart[(g * NCHK + c) * DD * PG], lane, warp);

    // ---------- gate B + last-block epilogue ----------
    __syncthreads();
    __threadfence();
    if (tid == 0) {
        unsigned old = atomicAdd(&g_cntB[g], 1u);
        slast = (old == NCHK - 1);
    }
    __syncthreads();
    if (!slast) return;

    if (tid < DD * PG) {
        float s = 0.f;
        #pragma unroll
        for (int cc = 0; cc < NCHK; ++cc)
            s += __ldcg(&g_cpart[(g * NCHK + cc) * DD * PG + tid]);
        int d = tid >> 3, p = tid & 7;
        csh[p * DD + d] = -s;
    }
    __syncthreads();
    if (warp < PG) {
        int p = warp;
        float c0 = csh[p * DD + lane], c1 = csh[p * DD + 32 + lane];
        float s = c0 * c0 + c1 * c1;
        #pragma unroll
        for (int o = 16; o; o >>= 1) s += __shfl_xor_sync(0xffffffffu, s, o);
        if (lane == 0) red[p] = fminf(sqrtf(s), 0.1f) * 0.1f;
    }
    __syncthreads();
    if (tid < DD * PG) {
        int p = tid >> 6, m = tid & (DD - 1);
        if (p < nsPerB) {
            float t = (float)(p + 1) * invn1;
            float tfac = t * (1.0f - t);
            float xv = x0g[m] + t * dlt[m];
            out[((p + 1) * B + g) * DD + m] = xv + csh[p * DD + m] * tfac * red[p];
        }
    }
    if (tid == 0) {                      // reset for next graph replay
        g_cntA[g] = 0;
        g_cntB[g] = 0;
        __threadfence();
    }
}

extern "C" void kernel_launch(void* const* d_in, const int* in_sizes, int n_in,
                              void* d_out, int out_size)
{
    const float* x0 = (const float*)d_in[0];
    const float* xT = (const float*)d_in[1];
    const float* W1 = (const float*)d_in[2];
    const float* b1 = (const float*)d_in[3];
    const float* W2 = (const float*)d_in[4];
    float* out = (float*)d_out;

    int H = in_sizes[3];               // 2048
    int Dd = in_sizes[2] / H;          // 64
    int B = in_sizes[0] / Dd;          // 32
    int O = in_sizes[5];               // 64
    int n_steps = out_size / (B * Dd); // 10
    int nInterior = (n_steps - 2) * B; // 256

    if (nInterior <= 0) return;

    size_t smem = (size_t)(DD * LD + CCH + 2 * PG * LD + 2 * CCH
                           + 2 * DD * PG + 2 * DD + 16) * sizeof(float);
    static int attr_set = 0;
    if (!attr_set) {
        cudaFuncSetAttribute(geo_one, cudaFuncAttributeMaxDynamicSharedMemorySize, (int)smem);
        attr_set = 1;
    }
    dim3 grid(B, NCHK);
    geo_one<<<grid, NT, smem>>>(x0, xT, W1, b1, W2, out, B, O, n_steps, nInterior);
}

// round 12
// speedup vs baseline: 1.0077x; 1.0077x over previous
#include <cuda_runtime.h>

#define NT    1024
#define PG    8                  // points per group (= n_steps-2 here)
#define DD    64
#define HH    2048
#define CCH   512                // chunk columns
#define LD    516                // padded row stride (floats): 516*4=2064B, 16B-aligned, 4 mod 32 banks
#define NCHK  4
#define MAXB  64

__device__ float g_wpart[MAXB * NCHK * DD * PG];
__device__ float g_cpart[MAXB * NCHK * DD * PG];
__device__ unsigned g_cntA[MAXB];
__device__ unsigned g_cntB[MAXB];

__device__ __forceinline__ float tanh_fast(float x)
{
    float y;
    asm("tanh.approx.f32 %0, %1;" : "=f"(y) : "f"(x));
    return y;
}

// stage one 64x512 W1 tile into smem rows of stride LD (cols 512..515 unused)
__device__ __forceinline__ void load_chunk_async(float* buf, const float* __restrict__ W1,
                                                 int j0, int tid)
{
    #pragma unroll
    for (int s = 0; s < 8; ++s) {
        int seg = s * NT + tid;          // 8192 16B segments
        int row = seg >> 7;              // 0..63
        int k   = seg & 127;             // 16B segment within row
        const float* src = W1 + row * HH + j0 + k * 4;
        unsigned dst = (unsigned)__cvta_generic_to_shared(buf + row * LD + k * 4);
        asm volatile("cp.async.cg.shared.global [%0], [%1], 16;" :: "r"(dst), "l"(src));
    }
    asm volatile("cp.async.commit_group;");
}

// Register-tiled row pass: warp = 4row x 4p tile, lane = j-slice.
// Per j: 8 scalar LDS (all-32-bank striped) -> 16 FFMA. 2 MAC/read.
__device__ __forceinline__ void row_pass(const float* __restrict__ W1s,
                                         const float* __restrict__ src_p,   // [p][LD]
                                         float* __restrict__ dstg,          // [DD*PG]
                                         int lane, int warp)
{
    int r0 = (warp >> 1) * 4;            // 16 rowgroups
    int p0 = (warp & 1) * 4;             // 2 pgroups
    float acc[4][4];
    #pragma unroll
    for (int r = 0; r < 4; ++r)
        #pragma unroll
        for (int p = 0; p < 4; ++p) acc[r][p] = 0.f;

    #pragma unroll 4
    for (int jj = 0; jj < 16; ++jj) {
        int j = jj * 32 + lane;
        float wv[4], av[4];
        #pragma unroll
        for (int r = 0; r < 4; ++r) wv[r] = W1s[(r0 + r) * LD + j];
        #pragma unroll
        for (int p = 0; p < 4; ++p) av[p] = src_p[(p0 + p) * LD + j];
        #pragma unroll
        for (int r = 0; r < 4; ++r)
            #pragma unroll
            for (int p = 0; p < 4; ++p)
                acc[r][p] += wv[r] * av[p];
    }
    // reduce each acc across the 32 j-slices; static indices only
    #pragma unroll
    for (int r = 0; r < 4; ++r)
        #pragma unroll
        for (int p = 0; p < 4; ++p) {
            float v = acc[r][p];
            #pragma unroll
            for (int o = 16; o; o >>= 1) v += __shfl_xor_sync(0xffffffffu, v, o);
            acc[r][p] = v;
        }
    #pragma unroll
    for (int r = 0; r < 4; ++r)
        #pragma unroll
        for (int p = 0; p < 4; ++p)
            if (lane == r * 4 + p)
                dstg[(r0 + r) * PG + p0 + p] = acc[r][p];
}

__global__ __launch_bounds__(NT, 1) void geo_one(
    const float* __restrict__ x0, const float* __restrict__ xT,
    const float* __restrict__ W1, const float* __restrict__ b1,
    const float* __restrict__ W2, float* __restrict__ out,
    int B, int O, int n_steps, int nInterior)
{
    extern __shared__ float sm[];
    float* W1s   = sm;                   // DD*LD = 33024
    float* a_sh  = W1s + DD * LD;        // 512
    float* asp_p = a_sh + CCH;           // [p][LD] : 8*516
    float* as_p  = asp_p + PG * LD;      // 8*516
    float* ue    = as_p + PG * LD;       // [2][512]
    float* wp    = ue + 2 * CCH;         // [d][p] : 512
    float* csh   = wp + DD * PG;         // [p][d] : 512
    float* x0g   = csh + PG * DD;        // 64
    float* dlt   = x0g + DD;             // 64
    float* red   = dlt + DD;             // 16
    __shared__ int slast;

    int tid = threadIdx.x, lane = tid & 31, warp = tid >> 5;
    int g = blockIdx.x;                  // batch index
    int c = blockIdx.y;                  // W1 chunk
    int j0 = c * CCH;
    int nsPerB = n_steps - 2;            // <= PG
    float invn1 = 1.0f / (float)(n_steps - 1);

    load_chunk_async(W1s, W1, j0, tid);

    // ---------- prep ----------
    if (tid < DD) {
        float a0 = x0[g * DD + tid];
        float aT = xT[g * DD + tid];
        x0g[tid] = a0;
        dlt[tid] = aT - a0;
        if (c == 0) {
            out[g * DD + tid] = a0;
            out[((n_steps - 1) * B + g) * DD + tid] = aT;
        }
    }
    __syncthreads();
    if (warp == 0) {
        float s = dlt[lane] * dlt[lane] + dlt[lane + 32] * dlt[lane + 32];
        #pragma unroll
        for (int o = 16; o; o >>= 1) s += __shfl_xor_sync(0xffffffffu, s, o);
        if (lane == 0) red[0] = 1.0f / sqrtf(s);
    }
    __syncthreads();

    // a_j = inv * (W2[j,:] . dlt) for this chunk's 512 j
    if (tid < CCH) {
        float inv = red[0];
        const float4* w2r = (const float4*)(W2 + (size_t)(j0 + tid) * O);
        const float4* v4  = (const float4*)dlt;
        float acc = 0.f;
        #pragma unroll
        for (int k = 0; k < DD / 4; ++k) {
            float4 w = w2r[k], vv = v4[k];
            acc += w.x * vv.x + w.y * vv.y + w.z * vv.z + w.w * vv.w;
        }
        a_sh[tid] = acc * inv;
    }
    asm volatile("cp.async.wait_group 0;");
    __syncthreads();

    int j   = tid & (CCH - 1);
    int ph  = tid >> 9;                  // 0 or 1

    // ---------- phase A column: u_j (ph=0) / e_j (ph=1) ----------
    {
        const float* src = ph ? dlt : x0g;
        float acc = ph ? 0.f : b1[j0 + j];
        #pragma unroll 8
        for (int d = 0; d < DD; ++d)
            acc += src[d] * W1s[d * LD + j];
        ue[ph * CCH + j] = acc;
    }
    __syncthreads();

    // as/asp for this thread's 4 points
    {
        float u = ue[j], e = ue[CCH + j];
        float a = a_sh[j];
        #pragma unroll
        for (int k = 0; k < 4; ++k) {
            int p = ph * 4 + k;
            int pc = (p < nsPerB) ? p : (nsPerB - 1);
            float tpar = (float)(pc + 1) * invn1;
            float t = tanh_fast(u + tpar * e);
            float sf = 1.0f - t * t;
            as_p[p * LD + j]  = a * sf;
            asp_p[p * LD + j] = a * (-2.0f * t * sf);
        }
    }
    __syncthreads();

    // ---------- phase A row: partial w ----------
    row_pass(W1s, as_p, &g_wpart[(g * NCHK + c) * DD * PG], lane, warp);

    // ---------- gate A ----------
    __syncthreads();
    __threadfence();
    if (tid == 0) {
        atomicAdd(&g_cntA[g], 1u);
        while (((volatile unsigned*)g_cntA)[g] < NCHK) __nanosleep(20);
    }
    __syncthreads();

    // ---------- phase B: reduce w ; q ; m ----------
    if (tid < DD * PG) {
        float s = 0.f;
        #pragma unroll
        for (int cc = 0; cc < NCHK; ++cc)
            s += __ldcg(&g_wpart[(g * NCHK + cc) * DD * PG + tid]);
        wp[tid] = s;
    }
    __syncthreads();

    {
        float q0 = 0.f, q1 = 0.f, q2 = 0.f, q3 = 0.f;
        const float4* wp4 = (const float4*)wp;
        #pragma unroll 8
        for (int d = 0; d < DD; ++d) {
            float wv = W1s[d * LD + j];
            float4 wc = wp4[d * 2 + ph];
            q0 += wc.x * wv; q1 += wc.y * wv; q2 += wc.z * wv; q3 += wc.w * wv;
        }
        float qv[4] = {q0, q1, q2, q3};
        #pragma unroll
        for (int k = 0; k < 4; ++k) {
            int p = ph * 4 + k;
            as_p[p * LD + j] = asp_p[p * LD + j] * qv[k];
        }
    }
    __syncthreads();

    // ---------- phase B row: partial corr ----------
    row_pass(W1s, as_p, &g_cpart[(g * NCHK + c) * DD * PG], lane, warp);

    // ---------- gate B + last-block epilogue ----------
    __syncthreads();
    __threadfence();
    if (tid == 0) {
        unsigned old = atomicAdd(&g_cntB[g], 1u);
        slast = (old == NCHK - 1);
    }
    __syncthreads();
    if (!slast) return;

    if (tid < DD * PG) {
        float s = 0.f;
        #pragma unroll
        for (int cc = 0; cc < NCHK; ++cc)
            s += __ldcg(&g_cpart[(g * NCHK + cc) * DD * PG + tid]);
        int d = tid >> 3, p = tid & 7;
        csh[p * DD + d] = -s;
    }
    __syncthreads();
    if (warp < PG) {
        int p = warp;
        float c0 = csh[p * DD + lane], c1 = csh[p * DD + 32 + lane];
        float s = c0 * c0 + c1 * c1;
        #pragma unroll
        for (int o = 16; o; o >>= 1) s += __shfl_xor_sync(0xffffffffu, s, o);
        if (lane == 0) red[p] = fminf(sqrtf(s), 0.1f) * 0.1f;
    }
    __syncthreads();
    if (tid < DD * PG) {
        int p = tid >> 6, m = tid & (DD - 1);
        if (p < nsPerB) {
            float t = (float)(p + 1) * invn1;
            float tfac = t * (1.0f - t);
            float xv = x0g[m] + t * dlt[m];
            out[((p + 1) * B + g) * DD + m] = xv + csh[p * DD + m] * tfac * red[p];
        }
    }
    if (tid == 0) {                      // reset for next graph replay
        g_cntA[g] = 0;
        g_cntB[g] = 0;
        __threadfence();
    }
}

extern "C" void kernel_launch(void* const* d_in, const int* in_sizes, int n_in,
                              void* d_out, int out_size)
{
    const float* x0 = (const float*)d_in[0];
    const float* xT = (const float*)d_in[1];
    const float* W1 = (const float*)d_in[2];
    const float* b1 = (const float*)d_in[3];
    const float* W2 = (const float*)d_in[4];
    float* out = (float*)d_out;

    int H = in_sizes[3];               // 2048
    int Dd = in_sizes[2] / H;          // 64
    int B = in_sizes[0] / Dd;          // 32
    int O = in_sizes[5];               // 64
    int n_steps = out_size / (B * Dd); // 10
    int nInterior = (n_steps - 2) * B; // 256

    if (nInterior <= 0) return;

    size_t smem = (size_t)(DD * LD + CCH + 2 * PG * LD + 2 * CCH
                           + 2 * DD * PG + 2 * DD + 16) * sizeof(float);
    static int attr_set = 0;
    if (!attr_set) {
        cudaFuncSetAttribute(geo_one, cudaFuncAttributeMaxDynamicSharedMemorySize, (int)smem);
        attr_set = 1;
    }
    dim3 grid(B, NCHK);
    geo_one<<<grid, NT, smem>>>(x0, xT, W1, b1, W2, out, B, O, n_steps, nInterior);
}

// round 13
// speedup vs baseline: 1.0727x; 1.0645x over previous
#include <cuda_runtime.h>

#define NT    256
#define PG    8                  // points per group (= n_steps-2 here)
#define DD    64
#define HH    2048
#define CCH   256
#define CCHP  264                // activation stride: 8-bank offset per p, 16B-aligned
#define LD    260                // W1s row stride: 4 mod 32 banks, 16B-aligned
#define LD4   65                 // in float4/ulonglong2
#define NCHK  8
#define MAXB  64

__device__ float g_wpart[MAXB * NCHK * DD * PG];
__device__ float g_cpart[MAXB * NCHK * DD * PG];
__device__ unsigned g_cntA[MAXB];
__device__ unsigned g_cntB[MAXB];

__device__ __forceinline__ float tanh_fast(float x)
{
    float y;
    asm("tanh.approx.f32 %0, %1;" : "=f"(y) : "f"(x));
    return y;
}

// ---- packed f32x2 helpers ----
__device__ __forceinline__ unsigned long long pk2(float x, float y)
{
    unsigned long long r;
    asm("mov.b64 %0, {%1, %2};" : "=l"(r) : "f"(x), "f"(y));
    return r;
}
__device__ __forceinline__ void upk2(unsigned long long v, float& x, float& y)
{
    asm("mov.b64 {%0, %1}, %2;" : "=f"(x), "=f"(y) : "l"(v));
}
__device__ __forceinline__ unsigned long long ffma2(unsigned long long a,
                                                    unsigned long long b,
                                                    unsigned long long c)
{
    unsigned long long d;
    asm("fma.rn.f32x2 %0, %1, %2, %3;" : "=l"(d) : "l"(a), "l"(b), "l"(c));
    return d;
}

// stage one 64x256 W1 tile into smem rows of stride LD
__device__ __forceinline__ void load_chunk_async(float* buf, const float* __restrict__ W1,
                                                 int j0, int tid)
{
    #pragma unroll
    for (int s = 0; s < 16; ++s) {
        int g = s * NT + tid;            // 4096 16B segments
        int d = g >> 6;
        int k = g & 63;
        const float* src = W1 + d * HH + j0 + k * 4;
        unsigned dst = (unsigned)__cvta_generic_to_shared(buf + d * LD + k * 4);
        asm volatile("cp.async.cg.shared.global [%0], [%1], 16;" :: "r"(dst), "l"(src));
    }
    asm volatile("cp.async.commit_group;");
}

// row pass: lane owns (row, pA) and (row, pB=pA+4); packed f32x2 over j.
// Conflict-free: W rows stride 260 (4 mod 32), act slices stride 264 (8 mod 32).
__device__ __forceinline__ void row_pass(const float* __restrict__ W1s,
                                         const float* __restrict__ src_p,   // [p][CCHP]
                                         float* __restrict__ dstg,          // [DD*PG]
                                         int lane, int warp)
{
    int row = warp * 8 + (lane >> 2);
    int pA = lane & 3, pB = pA + 4;
    const ulonglong2* W4 = (const ulonglong2*)W1s;
    const ulonglong2* aA = (const ulonglong2*)(src_p + pA * CCHP);
    const ulonglong2* aB = (const ulonglong2*)(src_p + pB * CCHP);
    unsigned long long accA0 = 0ull, accA1 = 0ull, accB0 = 0ull, accB1 = 0ull;
    #pragma unroll 8
    for (int j4 = 0; j4 < CCH / 4; ++j4) {
        ulonglong2 w = W4[row * LD4 + j4];
        ulonglong2 a = aA[j4];
        ulonglong2 b = aB[j4];
        accA0 = ffma2(w.x, a.x, accA0);
        accA1 = ffma2(w.y, a.y, accA1);
        accB0 = ffma2(w.x, b.x, accB0);
        accB1 = ffma2(w.y, b.y, accB1);
    }
    float a0x, a0y, a1x, a1y, b0x, b0y, b1x, b1y;
    upk2(accA0, a0x, a0y); upk2(accA1, a1x, a1y);
    upk2(accB0, b0x, b0y); upk2(accB1, b1x, b1y);
    dstg[row * PG + pA] = (a0x + a0y) + (a1x + a1y);
    dstg[row * PG + pB] = (b0x + b0y) + (b1x + b1y);
}

__global__ __launch_bounds__(NT, 2) void geo_one(
    const float* __restrict__ x0, const float* __restrict__ xT,
    const float* __restrict__ W1, const float* __restrict__ b1,
    const float* __restrict__ W2, float* __restrict__ out,
    int B, int O, int n_steps, int nInterior)
{
    extern __shared__ float sm[];
    float* W1s   = sm;                   // DD*LD = 16640
    float* a_sh  = W1s + DD * LD;        // 256
    float* asp_p = a_sh + CCH;           // [p][CCHP] : 2112
    float* as_p  = asp_p + PG * CCHP;    // [p][CCHP] : 2112
    float* xp    = as_p + PG * CCHP;     // [d][p] : 512 (p contiguous)
    float* wp    = xp + DD * PG;         // [d][p] : 512
    float* csh   = wp + DD * PG;         // [p][d] : 512
    float* vsh   = csh + PG * DD;        // 64
    float* red   = vsh + DD;             // 16
    __shared__ int slast;

    int tid = threadIdx.x, lane = tid & 31, warp = tid >> 5;
    int g = blockIdx.x;                  // batch index
    int c = blockIdx.y;                  // W1 chunk
    int j0 = c * CCH;
    int nsPerB = n_steps - 2;            // <= PG
    float invn1 = 1.0f / (float)(n_steps - 1);

    load_chunk_async(W1s, W1, j0, tid);

    // ---------- prep ----------
    if (tid < DD) {
        float a0 = x0[g * DD + tid];
        float aT = xT[g * DD + tid];
        vsh[tid] = aT - a0;
        if (c == 0) {
            out[g * DD + tid] = a0;
            out[((n_steps - 1) * B + g) * DD + tid] = aT;
        }
    }
    __syncthreads();
    if (warp == 0) {
        float s = vsh[lane] * vsh[lane] + vsh[lane + 32] * vsh[lane + 32];
        #pragma unroll
        for (int o = 16; o; o >>= 1) s += __shfl_xor_sync(0xffffffffu, s, o);
        if (lane == 0) red[0] = 1.0f / sqrtf(s);
    }
    __syncthreads();

    // a_j = inv * (W2[j,:] . (xT-x0))
    {
        float inv = red[0];
        const float4* w2r = (const float4*)(W2 + (size_t)(j0 + tid) * O);
        const float4* v4  = (const float4*)vsh;
        float acc = 0.f;
        #pragma unroll
        for (int k = 0; k < DD / 4; ++k) {
            float4 w = w2r[k], vv = v4[k];
            acc += w.x * vv.x + w.y * vv.y + w.z * vv.z + w.w * vv.w;
        }
        a_sh[tid] = acc * inv;
    }

    // straight points -> xp[m][p] (p contiguous for packed loads)
    #pragma unroll
    for (int idx = tid; idx < DD * PG; idx += NT) {
        int m = idx >> 3, p = idx & 7;
        int pc = (p < nsPerB) ? p : (nsPerB - 1);
        float t = (float)(pc + 1) * invn1;
        float a0 = x0[g * DD + m];
        xp[m * PG + p] = a0 + t * (xT[g * DD + m] - a0);
    }
    asm volatile("cp.async.wait_group 0;");
    __syncthreads();

    // ---------- phase A column: h for 8 points, packed pairs ----------
    unsigned long long h01, h23, h45, h67;
    {
        float bj = b1[j0 + tid];
        unsigned long long b2 = pk2(bj, bj);
        h01 = h23 = h45 = h67 = b2;
    }
    {
        const ulonglong2* xp2 = (const ulonglong2*)xp;
        #pragma unroll 8
        for (int d = 0; d < DD; ++d) {
            float wv = W1s[d * LD + tid];
            unsigned long long w2 = pk2(wv, wv);
            ulonglong2 xa = xp2[d * 2], xb = xp2[d * 2 + 1];
            h01 = ffma2(w2, xa.x, h01);
            h23 = ffma2(w2, xa.y, h23);
            h45 = ffma2(w2, xb.x, h45);
            h67 = ffma2(w2, xb.y, h67);
        }
    }
    {
        float hv[PG];
        upk2(h01, hv[0], hv[1]); upk2(h23, hv[2], hv[3]);
        upk2(h45, hv[4], hv[5]); upk2(h67, hv[6], hv[7]);
        float a = a_sh[tid];
        #pragma unroll
        for (int p = 0; p < PG; ++p) {
            float t = tanh_fast(hv[p]);
            float sf = 1.0f - t * t;
            as_p[p * CCHP + tid]  = a * sf;
            asp_p[p * CCHP + tid] = a * (-2.0f * t * sf);
        }
    }
    __syncthreads();

    // ---------- phase A row: partial w ----------
    row_pass(W1s, as_p, &g_wpart[(g * NCHK + c) * DD * PG], lane, warp);

    // ---------- gate A ----------
    __syncthreads();
    __threadfence();
    if (tid == 0) {
        atomicAdd(&g_cntA[g], 1u);
        while (((volatile unsigned*)g_cntA)[g] < NCHK) __nanosleep(20);
    }
    __syncthreads();

    // ---------- phase B: reduce w ; q (packed) ; m ----------
    #pragma unroll
    for (int idx = tid; idx < DD * PG; idx += NT) {
        float s = 0.f;
        #pragma unroll
        for (int cc = 0; cc < NCHK; ++cc)
            s += __ldcg(&g_wpart[(g * NCHK + cc) * DD * PG + idx]);
        wp[idx] = s;
    }
    __syncthreads();

    {
        unsigned long long q01 = 0ull, q23 = 0ull, q45 = 0ull, q67 = 0ull;
        const ulonglong2* wp2 = (const ulonglong2*)wp;
        #pragma unroll 8
        for (int d = 0; d < DD; ++d) {
            float wv = W1s[d * LD + tid];
            unsigned long long w2 = pk2(wv, wv);
            ulonglong2 wa = wp2[d * 2], wb = wp2[d * 2 + 1];
            q01 = ffma2(w2, wa.x, q01);
            q23 = ffma2(w2, wa.y, q23);
            q45 = ffma2(w2, wb.x, q45);
            q67 = ffma2(w2, wb.y, q67);
        }
        float qv[PG];
        upk2(q01, qv[0], qv[1]); upk2(q23, qv[2], qv[3]);
        upk2(q45, qv[4], qv[5]); upk2(q67, qv[6], qv[7]);
        #pragma unroll
        for (int p = 0; p < PG; ++p)
            as_p[p * CCHP + tid] = asp_p[p * CCHP + tid] * qv[p];
    }
    __syncthreads();

    // ---------- phase B row: partial corr ----------
    row_pass(W1s, as_p, &g_cpart[(g * NCHK + c) * DD * PG], lane, warp);

    // ---------- gate B + last-block epilogue ----------
    __syncthreads();
    __threadfence();
    if (tid == 0) {
        unsigned old = atomicAdd(&g_cntB[g], 1u);
        slast = (old == NCHK - 1);
    }
    __syncthreads();
    if (!slast) return;

    #pragma unroll
    for (int idx = tid; idx < DD * PG; idx += NT) {
        float s = 0.f;
        #pragma unroll
        for (int cc = 0; cc < NCHK; ++cc)
            s += __ldcg(&g_cpart[(g * NCHK + cc) * DD * PG + idx]);
        int d = idx >> 3, p = idx & 7;
        csh[p * DD + d] = -s;
    }
    __syncthreads();
    if (warp < PG) {
        int p = warp;
        float c0 = csh[p * DD + lane], c1 = csh[p * DD + 32 + lane];
        float s = c0 * c0 + c1 * c1;
        #pragma unroll
        for (int o = 16; o; o >>= 1) s += __shfl_xor_sync(0xffffffffu, s, o);
        if (lane == 0) red[p] = fminf(sqrtf(s), 0.1f) * 0.1f;
    }
    __syncthreads();
    #pragma unroll
    for (int idx = tid; idx < DD * PG; idx += NT) {
        int p = idx >> 6, m = idx & (DD - 1);
        if (p < nsPerB) {
            float t = (float)(p + 1) * invn1;
            float tfac = t * (1.0f - t);
            float a0 = x0[g * DD + m];
            float xv = a0 + t * (xT[g * DD + m] - a0);
            out[((p + 1) * B + g) * DD + m] = xv + csh[p * DD + m] * tfac * red[p];
        }
    }
    if (tid == 0) {                      // reset for next graph replay
        g_cntA[g] = 0;
        g_cntB[g] = 0;
        __threadfence();
    }
}

extern "C" void kernel_launch(void* const* d_in, const int* in_sizes, int n_in,
                              void* d_out, int out_size)
{
    const float* x0 = (const float*)d_in[0];
    const float* xT = (const float*)d_in[1];
    const float* W1 = (const float*)d_in[2];
    const float* b1 = (const float*)d_in[3];
    const float* W2 = (const float*)d_in[4];
    float* out = (float*)d_out;

    int H = in_sizes[3];               // 2048
    int Dd = in_sizes[2] / H;          // 64
    int B = in_sizes[0] / Dd;          // 32
    int O = in_sizes[5];               // 64
    int n_steps = out_size / (B * Dd); // 10
    int nInterior = (n_steps - 2) * B; // 256

    if (nInterior <= 0) return;

    size_t smem = (size_t)(DD * LD + CCH + 2 * PG * CCHP + 2 * DD * PG
                           + PG * DD + DD + 16) * sizeof(float);
    static int attr_set = 0;
    if (!attr_set) {
        cudaFuncSetAttribute(geo_one, cudaFuncAttributeMaxDynamicSharedMemorySize, (int)smem);
        attr_set = 1;
    }
    dim3 grid(B, NCHK);
    geo_one<<<grid, NT, smem>>>(x0, xT, W1, b1, W2, out, B, O, n_steps, nInterior);
}